// round 5
// baseline (speedup 1.0000x reference)
#include <cuda_runtime.h>
#include <cuda_bf16.h>

#define N_NODES 50000
#define N_EDGES 1250000
#define HID 64
#define CDIM 128
#define NTILE 32
#define N_TILES ((N_NODES + NTILE - 1) / NTILE)      // 1563 = 521*3
#define SCAT_BLOCKS 444
#define GEMM_BLOCKS 148
#define TOTAL_BLOCKS (SCAT_BLOCKS + GEMM_BLOCKS)
#define TOTAL_ITEMS (16LL * N_EDGES)
#define SPLIT_ITEMS 17500000LL

#define SW_PAD 68   // weight row pad (words): conflict-free LDS.128, 16B aligned
#define SC_PAD 36   // activation row pad

// scratch: t1 = x @ W1[0:64] + b1
__device__ float d_t1[(size_t)N_NODES * HID];

// ---------------- f32x2 helpers (sm_103a packed fp32) ----------------------
typedef unsigned long long ull;
__device__ __forceinline__ ull pack2(float lo, float hi) {
    ull r; asm("mov.b64 %0, {%1, %2};" : "=l"(r) : "f"(lo), "f"(hi)); return r;
}
__device__ __forceinline__ void unpack2(ull v, float& lo, float& hi) {
    asm("mov.b64 {%0, %1}, %2;" : "=f"(lo), "=f"(hi) : "l"(v));
}
__device__ __forceinline__ ull fma2(ull a, ull b, ull c) {
    ull d; asm("fma.rn.f32x2 %0, %1, %2, %3;" : "=l"(d) : "l"(a), "l"(b), "l"(c));
    return d;
}

// ---------------------------------------------------------------------------
// scatter: sequential edge_attr stream + v4 reductions. Streaming loads (cs)
// keep the 320MB edge stream from evicting the 25.6MB atomic target in L2.
// ---------------------------------------------------------------------------
__device__ __forceinline__ void scatter_range(const int* __restrict__ row,
                                              const float4* __restrict__ attr4,
                                              float* __restrict__ combined,
                                              long long beg, long long end,
                                              long long idx0, long long stride) {
    int lane = threadIdx.x & 31;
    int g = (int)((beg + idx0) & 15);
    long long idx = beg + idx0;

    while (idx - lane + 31 < end) {
        int e = (int)(idx >> 4);
        int r;
        if ((lane & 15) == 0) r = __ldcs(row + e);
        r = __shfl_sync(0xffffffffu, r, lane & 16);
        float4 v = __ldcs(attr4 + idx);
        float* dst = combined + (size_t)r * CDIM + HID + g * 4;
        asm volatile("red.global.add.v4.f32 [%0], {%1, %2, %3, %4};"
                     :: "l"(dst), "f"(v.x), "f"(v.y), "f"(v.z), "f"(v.w)
                     : "memory");
        idx += stride;
    }
    if (idx < end) {
        int e = (int)(idx >> 4);
        int r = __ldcs(row + e);
        float4 v = __ldcs(attr4 + idx);
        float* dst = combined + (size_t)r * CDIM + HID + g * 4;
        asm volatile("red.global.add.v4.f32 [%0], {%1, %2, %3, %4};"
                     :: "l"(dst), "f"(v.x), "f"(v.y), "f"(v.z), "f"(v.w)
                     : "memory");
    }
}

// ---------------------------------------------------------------------------
// K1: fused scatter + t1-GEMM (+ combined[:,0:64] = x copy)
// ---------------------------------------------------------------------------
__global__ void scatter_gemm_kernel(const int* __restrict__ row,
                                    const float4* __restrict__ attr4,
                                    const float4* __restrict__ x4,
                                    const float* __restrict__ W1,
                                    const float* __restrict__ b1,
                                    float* __restrict__ combined) {
    int tid = threadIdx.x;

    if (blockIdx.x < SCAT_BLOCKS) {
        long long idx0 = (long long)blockIdx.x * 256 + tid;
        scatter_range(row, attr4, combined, 0, SPLIT_ITEMS,
                      idx0, (long long)SCAT_BLOCKS * 256);
        return;
    }

    extern __shared__ float4 smem4[];
    float*  sW  = (float*)smem4;                 // 64*64 floats
    float4* sx4 = smem4 + (HID * HID) / 4;       // 32*16 float4

    for (int i = tid; i < HID * HID; i += 256) sW[i] = W1[i];
    float bj = __ldg(b1 + (tid & 63));
    __syncthreads();

    int g = tid >> 6;
    int j = tid & 63;
    int bid = blockIdx.x - SCAT_BLOCKS;
    float4* comb4 = (float4*)combined;

    for (int tile = bid; tile < N_TILES; tile += GEMM_BLOCKS) {
        int node0 = tile * NTILE;
        for (int i = tid; i < NTILE * 16; i += 256) {
            int n = node0 + (i >> 4), q = i & 15;
            float4 v = make_float4(0.f, 0.f, 0.f, 0.f);
            if (n < N_NODES) {
                v = __ldg(x4 + (size_t)n * 16 + q);
                comb4[(size_t)n * 32 + q] = v;
            }
            sx4[i] = v;
        }
        __syncthreads();

        float acc[8];
        #pragma unroll
        for (int n = 0; n < 8; n++) acc[n] = bj;

        const float4* c0 = sx4 + g * 8 * 16;
        #pragma unroll 4
        for (int i4 = 0; i4 < 16; i4++) {
            float w0 = sW[(i4 * 4 + 0) * HID + j];
            float w1 = sW[(i4 * 4 + 1) * HID + j];
            float w2 = sW[(i4 * 4 + 2) * HID + j];
            float w3 = sW[(i4 * 4 + 3) * HID + j];
            #pragma unroll
            for (int n = 0; n < 8; n++) {
                float4 c = c0[n * 16 + i4];
                acc[n] = fmaf(c.x, w0, acc[n]);
                acc[n] = fmaf(c.y, w1, acc[n]);
                acc[n] = fmaf(c.z, w2, acc[n]);
                acc[n] = fmaf(c.w, w3, acc[n]);
            }
        }
        #pragma unroll
        for (int n = 0; n < 8; n++) {
            int node = node0 + g * 8 + n;
            if (node < N_NODES) d_t1[(size_t)node * HID + j] = acc[n];
        }
        __syncthreads();
    }

    long long idx0 = (long long)bid * 256 + tid;
    scatter_range(row, attr4, combined, SPLIT_ITEMS, TOTAL_ITEMS,
                  idx0, (long long)GEMM_BLOCKS * 256);
}

// ---------------------------------------------------------------------------
// K2: out = silu(t1 + agg @ W1b) @ W2 + b2   — f32x2 packed version.
// Activations stored TRANSPOSED in smem (scT[k][node], shT[k][node]) so a
// single ld.shared.v2.u64 yields two node-pairs already packed for fma2.
// Weights transposed (sWT[j][k], rows padded to 68) -> LDS.128 per 4 k.
// Grid = 521 blocks x exactly 3 tiles = one balanced wave.
// ---------------------------------------------------------------------------
__global__ void mlp2_kernel(const float* __restrict__ combined,
                            const float* __restrict__ W1,
                            const float* __restrict__ W2,
                            const float* __restrict__ b2,
                            float* __restrict__ out) {
    extern __shared__ float smem[];
    float* sW1T = smem;                         // [64][SW_PAD]
    float* sW2T = sW1T + HID * SW_PAD;          // [64][SW_PAD]
    float* scT  = sW2T + HID * SW_PAD;          // [64][SC_PAD]
    float* shT  = scT  + HID * SC_PAD;          // [64][SC_PAD]

    int tid = threadIdx.x;

    // stage transposed weights: sWT[j][k] = W[k][j]
    for (int i = tid; i < HID * HID; i += 256) {
        int k = i >> 6, j = i & 63;
        sW1T[j * SW_PAD + k] = W1[(HID + k) * HID + j];   // W1b = W1[64:128]
        sW2T[j * SW_PAD + k] = W2[k * HID + j];
    }
    float b2j = __ldg(b2 + (tid & 63));
    ull b2d = pack2(b2j, b2j);
    __syncthreads();

    int g = tid >> 6;          // node-subgroup 0..3 (8 nodes each)
    int j = tid & 63;          // feature
    const float4* comb4 = (const float4*)combined;

    #pragma unroll 1
    for (int it = 0; it < 3; it++) {
        int tile  = blockIdx.x * 3 + it;
        int node0 = tile * NTILE;

        // ---- stage agg transposed: scT[k][n] = combined[node0+n][64+k] ----
        for (int s = tid; s < NTILE * 16; s += 256) {
            int n = s >> 4, q = s & 15;
            int node = node0 + n;
            float4 v = (node < N_NODES)
                         ? __ldg(comb4 + (size_t)node * 32 + 16 + q)
                         : make_float4(0.f, 0.f, 0.f, 0.f);
            scT[(q * 4 + 0) * SC_PAD + n] = v.x;
            scT[(q * 4 + 1) * SC_PAD + n] = v.y;
            scT[(q * 4 + 2) * SC_PAD + n] = v.z;
            scT[(q * 4 + 3) * SC_PAD + n] = v.w;
        }
        __syncthreads();

        // ---- layer 1b: A = t1 + agg @ W1b  (pairs of nodes in f32x2) ----
        int nb = node0 + g * 8;
        ull A[4];
        #pragma unroll
        for (int p = 0; p < 4; p++) {
            int n0 = nb + 2 * p;
            float t0 = (n0     < N_NODES) ? d_t1[(size_t)n0 * HID + j]       : 0.f;
            float t1v = (n0 + 1 < N_NODES) ? d_t1[(size_t)(n0 + 1) * HID + j] : 0.f;
            A[p] = pack2(t0, t1v);
        }
        const float* wrow1 = sW1T + j * SW_PAD;
        #pragma unroll 4
        for (int k4 = 0; k4 < 16; k4++) {
            float4 w = *(const float4*)(wrow1 + k4 * 4);
            #pragma unroll
            for (int kk = 0; kk < 4; kk++) {
                float wk = (&w.x)[kk];
                ull wd = pack2(wk, wk);
                const ulonglong2* cp =
                    (const ulonglong2*)(scT + (k4 * 4 + kk) * SC_PAD + g * 8);
                ulonglong2 cA = cp[0];
                ulonglong2 cB = cp[1];
                A[0] = fma2(cA.x, wd, A[0]);
                A[1] = fma2(cA.y, wd, A[1]);
                A[2] = fma2(cB.x, wd, A[2]);
                A[3] = fma2(cB.y, wd, A[3]);
            }
        }

        // ---- SiLU, store h transposed: shT[j][nodes] ----
        ull H[4];
        #pragma unroll
        for (int p = 0; p < 4; p++) {
            float a0, a1;
            unpack2(A[p], a0, a1);
            float h0 = __fdividef(a0, 1.0f + __expf(-a0));
            float h1 = __fdividef(a1, 1.0f + __expf(-a1));
            H[p] = pack2(h0, h1);
        }
        {
            ulonglong2* hp = (ulonglong2*)(shT + j * SC_PAD + g * 8);
            hp[0] = make_ulonglong2(H[0], H[1]);
            hp[1] = make_ulonglong2(H[2], H[3]);
        }
        __syncthreads();

        // ---- layer 2: B = b2 + h @ W2 ----
        ull B[4];
        #pragma unroll
        for (int p = 0; p < 4; p++) B[p] = b2d;
        const float* wrow2 = sW2T + j * SW_PAD;
        #pragma unroll 4
        for (int k4 = 0; k4 < 16; k4++) {
            float4 w = *(const float4*)(wrow2 + k4 * 4);
            #pragma unroll
            for (int kk = 0; kk < 4; kk++) {
                float wk = (&w.x)[kk];
                ull wd = pack2(wk, wk);
                const ulonglong2* cp =
                    (const ulonglong2*)(shT + (k4 * 4 + kk) * SC_PAD + g * 8);
                ulonglong2 cA = cp[0];
                ulonglong2 cB = cp[1];
                B[0] = fma2(cA.x, wd, B[0]);
                B[1] = fma2(cA.y, wd, B[1]);
                B[2] = fma2(cB.x, wd, B[2]);
                B[3] = fma2(cB.y, wd, B[3]);
            }
        }
        #pragma unroll
        for (int p = 0; p < 4; p++) {
            float o0, o1;
            unpack2(B[p], o0, o1);
            int n0 = nb + 2 * p;
            if (n0     < N_NODES) out[(size_t)n0 * HID + j]       = o0;
            if (n0 + 1 < N_NODES) out[(size_t)(n0 + 1) * HID + j] = o1;
        }
        __syncthreads();   // protect scT/shT before next tile
    }
}

// ---------------------------------------------------------------------------
extern "C" void kernel_launch(void* const* d_in, const int* in_sizes, int n_in,
                              void* d_out, int out_size) {
    const int*   edge_index = (const int*)d_in[0];
    const float* edge_attr  = (const float*)d_in[1];
    const float* x          = (const float*)d_in[2];
    const float* W1         = (const float*)d_in[3];
    const float* b1         = (const float*)d_in[4];
    const float* W2         = (const float*)d_in[5];
    const float* b2         = (const float*)d_in[6];

    float* out      = (float*)d_out;
    float* combined = out + (size_t)N_NODES * HID;

    cudaMemsetAsync(combined, 0, (size_t)N_NODES * CDIM * sizeof(float));

    {
        int smem = (HID * HID) * 4 + NTILE * 16 * 16;
        cudaFuncSetAttribute(scatter_gemm_kernel,
                             cudaFuncAttributeMaxDynamicSharedMemorySize, smem);
        scatter_gemm_kernel<<<TOTAL_BLOCKS, 256, smem>>>(
            edge_index, (const float4*)edge_attr, (const float4*)x,
            W1, b1, combined);
    }

    {
        int smem = (2 * HID * SW_PAD + 2 * HID * SC_PAD) * (int)sizeof(float);
        cudaFuncSetAttribute(mlp2_kernel,
                             cudaFuncAttributeMaxDynamicSharedMemorySize, smem);
        mlp2_kernel<<<N_TILES / 3, 256, smem>>>(combined, W1, W2, b2, out);
    }
}

// round 6
// speedup vs baseline: 1.2184x; 1.2184x over previous
#include <cuda_runtime.h>
#include <cuda_bf16.h>

#define N_NODES 50000
#define N_EDGES 1250000
#define HID 64
#define CDIM 128
#define NTILE 32                                     // K1 GEMM tile
#define N_TILES ((N_NODES + NTILE - 1) / NTILE)
#define SCAT_BLOCKS 444
#define GEMM_BLOCKS 148
#define TOTAL_BLOCKS (SCAT_BLOCKS + GEMM_BLOCKS)
#define TOTAL_ITEMS (16LL * N_EDGES)
#define SPLIT_ITEMS 17500000LL

#define NT2 64                                       // mlp2 nodes per tile
#define N2_TILES ((N_NODES + NT2 - 1) / NT2)         // 782
#define SW_PAD 68   // weight row pad (words)
#define SC_PAD 66   // activation row pad (words): 8B-aligned u64, ~4-way STS ok

// scratch: t1 = x @ W1[0:64] + b1
__device__ float d_t1[(size_t)N_NODES * HID];

// ---------------- f32x2 helpers --------------------------------------------
typedef unsigned long long ull;
__device__ __forceinline__ ull pack2(float lo, float hi) {
    ull r; asm("mov.b64 %0, {%1, %2};" : "=l"(r) : "f"(lo), "f"(hi)); return r;
}
__device__ __forceinline__ void unpack2(ull v, float& lo, float& hi) {
    asm("mov.b64 {%0, %1}, %2;" : "=f"(lo), "=f"(hi) : "l"(v));
}
__device__ __forceinline__ ull fma2(ull a, ull b, ull c) {
    ull d; asm("fma.rn.f32x2 %0, %1, %2, %3;" : "=l"(d) : "l"(a), "l"(b), "l"(c));
    return d;
}

// ---------------------------------------------------------------------------
// scatter: sequential edge_attr stream + v4 reductions (default-cached loads)
// ---------------------------------------------------------------------------
__device__ __forceinline__ void scatter_range(const int* __restrict__ row,
                                              const float4* __restrict__ attr4,
                                              float* __restrict__ combined,
                                              long long beg, long long end,
                                              long long idx0, long long stride) {
    int lane = threadIdx.x & 31;
    int g = (int)((beg + idx0) & 15);
    long long idx = beg + idx0;

    while (idx - lane + 31 < end) {
        int e = (int)(idx >> 4);
        int r;
        if ((lane & 15) == 0) r = __ldg(row + e);
        r = __shfl_sync(0xffffffffu, r, lane & 16);
        float4 v = __ldg(attr4 + idx);
        float* dst = combined + (size_t)r * CDIM + HID + g * 4;
        asm volatile("red.global.add.v4.f32 [%0], {%1, %2, %3, %4};"
                     :: "l"(dst), "f"(v.x), "f"(v.y), "f"(v.z), "f"(v.w)
                     : "memory");
        idx += stride;
    }
    if (idx < end) {
        int e = (int)(idx >> 4);
        int r = __ldg(row + e);
        float4 v = __ldg(attr4 + idx);
        float* dst = combined + (size_t)r * CDIM + HID + g * 4;
        asm volatile("red.global.add.v4.f32 [%0], {%1, %2, %3, %4};"
                     :: "l"(dst), "f"(v.x), "f"(v.y), "f"(v.z), "f"(v.w)
                     : "memory");
    }
}

// ---------------------------------------------------------------------------
// K1: fused scatter + t1-GEMM (+ combined[:,0:64] = x copy)
// ---------------------------------------------------------------------------
__global__ void scatter_gemm_kernel(const int* __restrict__ row,
                                    const float4* __restrict__ attr4,
                                    const float4* __restrict__ x4,
                                    const float* __restrict__ W1,
                                    const float* __restrict__ b1,
                                    float* __restrict__ combined) {
    int tid = threadIdx.x;

    if (blockIdx.x < SCAT_BLOCKS) {
        long long idx0 = (long long)blockIdx.x * 256 + tid;
        scatter_range(row, attr4, combined, 0, SPLIT_ITEMS,
                      idx0, (long long)SCAT_BLOCKS * 256);
        return;
    }

    extern __shared__ float4 smem4[];
    float*  sW  = (float*)smem4;
    float4* sx4 = smem4 + (HID * HID) / 4;

    for (int i = tid; i < HID * HID; i += 256) sW[i] = W1[i];
    float bj = __ldg(b1 + (tid & 63));
    __syncthreads();

    int g = tid >> 6;
    int j = tid & 63;
    int bid = blockIdx.x - SCAT_BLOCKS;
    float4* comb4 = (float4*)combined;

    for (int tile = bid; tile < N_TILES; tile += GEMM_BLOCKS) {
        int node0 = tile * NTILE;
        for (int i = tid; i < NTILE * 16; i += 256) {
            int n = node0 + (i >> 4), q = i & 15;
            float4 v = make_float4(0.f, 0.f, 0.f, 0.f);
            if (n < N_NODES) {
                v = __ldg(x4 + (size_t)n * 16 + q);
                comb4[(size_t)n * 32 + q] = v;
            }
            sx4[i] = v;
        }
        __syncthreads();

        float acc[8];
        #pragma unroll
        for (int n = 0; n < 8; n++) acc[n] = bj;

        const float4* c0 = sx4 + g * 8 * 16;
        #pragma unroll 4
        for (int i4 = 0; i4 < 16; i4++) {
            float w0 = sW[(i4 * 4 + 0) * HID + j];
            float w1 = sW[(i4 * 4 + 1) * HID + j];
            float w2 = sW[(i4 * 4 + 2) * HID + j];
            float w3 = sW[(i4 * 4 + 3) * HID + j];
            #pragma unroll
            for (int n = 0; n < 8; n++) {
                float4 c = c0[n * 16 + i4];
                acc[n] = fmaf(c.x, w0, acc[n]);
                acc[n] = fmaf(c.y, w1, acc[n]);
                acc[n] = fmaf(c.z, w2, acc[n]);
                acc[n] = fmaf(c.w, w3, acc[n]);
            }
        }
        #pragma unroll
        for (int n = 0; n < 8; n++) {
            int node = node0 + g * 8 + n;
            if (node < N_NODES) d_t1[(size_t)node * HID + j] = acc[n];
        }
        __syncthreads();
    }

    long long idx0 = (long long)bid * 256 + tid;
    scatter_range(row, attr4, combined, SPLIT_ITEMS, TOTAL_ITEMS,
                  idx0, (long long)GEMM_BLOCKS * 256);
}

// ---------------------------------------------------------------------------
// K2: out = silu(t1 + agg @ W1b) @ W2 + b2
// 64-node tile; thread = 8 nodes (group g) x 2 features (j, j+32).
// Activations transposed in smem, broadcast u64 loads feed f32x2 FMAs.
// h overlays the agg buffer (temporally disjoint) -> 4 blocks/SM.
// ---------------------------------------------------------------------------
__global__ void mlp2_kernel(const float* __restrict__ combined,
                            const float* __restrict__ W1,
                            const float* __restrict__ W2,
                            const float* __restrict__ b2,
                            float* __restrict__ out) {
    extern __shared__ float smem[];
    float* sW1T = smem;                         // [64][SW_PAD]
    float* sW2T = sW1T + HID * SW_PAD;          // [64][SW_PAD]
    float* scT  = sW2T + HID * SW_PAD;          // [64][SC_PAD] (agg, then h)

    int tid = threadIdx.x;

    for (int i = tid; i < HID * HID; i += 256) {
        int k = i >> 6, j = i & 63;
        sW1T[j * SW_PAD + k] = W1[(HID + k) * HID + j];   // W1b
        sW2T[j * SW_PAD + k] = W2[k * HID + j];
    }

    int g  = tid >> 5;          // node subgroup 0..7 (8 nodes)
    int j  = tid & 31;          // feature a
    int j2 = j + 32;            // feature b
    float b2a = __ldg(b2 + j);
    float b2b = __ldg(b2 + j2);
    ull b2da = pack2(b2a, b2a);
    ull b2db = pack2(b2b, b2b);

    const float4* comb4 = (const float4*)combined;
    int node0 = blockIdx.x * NT2;
    int nb = node0 + g * 8;

    // ---- stage agg transposed: scT[k][n] = combined[node0+n][64+k] ----
    for (int s = tid; s < NT2 * 16; s += 256) {
        int n = s >> 4, q = s & 15;
        int node = node0 + n;
        float4 v = (node < N_NODES)
                     ? __ldg(comb4 + (size_t)node * 32 + 16 + q)
                     : make_float4(0.f, 0.f, 0.f, 0.f);
        scT[(q * 4 + 0) * SC_PAD + n] = v.x;
        scT[(q * 4 + 1) * SC_PAD + n] = v.y;
        scT[(q * 4 + 2) * SC_PAD + n] = v.z;
        scT[(q * 4 + 3) * SC_PAD + n] = v.w;
    }

    // ---- t1 prefetch (global, coalesced over j) ----
    ull A0[4], A1[4];
    #pragma unroll
    for (int p = 0; p < 4; p++) {
        int n0 = nb + 2 * p;
        float a0 = 0.f, a1 = 0.f, c0 = 0.f, c1 = 0.f;
        if (n0 < N_NODES) {
            a0 = d_t1[(size_t)n0 * HID + j];
            c0 = d_t1[(size_t)n0 * HID + j2];
        }
        if (n0 + 1 < N_NODES) {
            a1 = d_t1[(size_t)(n0 + 1) * HID + j];
            c1 = d_t1[(size_t)(n0 + 1) * HID + j2];
        }
        A0[p] = pack2(a0, a1);
        A1[p] = pack2(c0, c1);
    }
    __syncthreads();

    // ---- layer 1b ----
    {
        const float* wra = sW1T + j  * SW_PAD;
        const float* wrb = sW1T + j2 * SW_PAD;
        #pragma unroll 4
        for (int k4 = 0; k4 < 16; k4++) {
            float4 wa = *(const float4*)(wra + k4 * 4);
            float4 wb = *(const float4*)(wrb + k4 * 4);
            #pragma unroll
            for (int kk = 0; kk < 4; kk++) {
                const float* base = scT + (k4 * 4 + kk) * SC_PAD + g * 8;
                ull c0 = *(const ull*)(base + 0);
                ull c1 = *(const ull*)(base + 2);
                ull c2 = *(const ull*)(base + 4);
                ull c3 = *(const ull*)(base + 6);
                float wka = (&wa.x)[kk];
                float wkb = (&wb.x)[kk];
                ull wda = pack2(wka, wka);
                ull wdb = pack2(wkb, wkb);
                A0[0] = fma2(c0, wda, A0[0]);
                A0[1] = fma2(c1, wda, A0[1]);
                A0[2] = fma2(c2, wda, A0[2]);
                A0[3] = fma2(c3, wda, A0[3]);
                A1[0] = fma2(c0, wdb, A1[0]);
                A1[1] = fma2(c1, wdb, A1[1]);
                A1[2] = fma2(c2, wdb, A1[2]);
                A1[3] = fma2(c3, wdb, A1[3]);
            }
        }
    }
    __syncthreads();   // all scT reads complete before overwrite with h

    // ---- SiLU; store h transposed into scT (reuse): scT[feat][n] ----
    #pragma unroll
    for (int p = 0; p < 4; p++) {
        float a0, a1, c0, c1;
        unpack2(A0[p], a0, a1);
        unpack2(A1[p], c0, c1);
        float h0 = __fdividef(a0, 1.0f + __expf(-a0));
        float h1 = __fdividef(a1, 1.0f + __expf(-a1));
        float h2 = __fdividef(c0, 1.0f + __expf(-c0));
        float h3 = __fdividef(c1, 1.0f + __expf(-c1));
        *(ull*)(scT + j  * SC_PAD + g * 8 + 2 * p) = pack2(h0, h1);
        *(ull*)(scT + j2 * SC_PAD + g * 8 + 2 * p) = pack2(h2, h3);
    }
    __syncthreads();

    // ---- layer 2 ----
    ull B0[4], B1[4];
    #pragma unroll
    for (int p = 0; p < 4; p++) { B0[p] = b2da; B1[p] = b2db; }
    {
        const float* wra = sW2T + j  * SW_PAD;
        const float* wrb = sW2T + j2 * SW_PAD;
        #pragma unroll 4
        for (int k4 = 0; k4 < 16; k4++) {
            float4 wa = *(const float4*)(wra + k4 * 4);
            float4 wb = *(const float4*)(wrb + k4 * 4);
            #pragma unroll
            for (int kk = 0; kk < 4; kk++) {
                const float* base = scT + (k4 * 4 + kk) * SC_PAD + g * 8;
                ull c0 = *(const ull*)(base + 0);
                ull c1 = *(const ull*)(base + 2);
                ull c2 = *(const ull*)(base + 4);
                ull c3 = *(const ull*)(base + 6);
                float wka = (&wa.x)[kk];
                float wkb = (&wb.x)[kk];
                ull wda = pack2(wka, wka);
                ull wdb = pack2(wkb, wkb);
                B0[0] = fma2(c0, wda, B0[0]);
                B0[1] = fma2(c1, wda, B0[1]);
                B0[2] = fma2(c2, wda, B0[2]);
                B0[3] = fma2(c3, wda, B0[3]);
                B1[0] = fma2(c0, wdb, B1[0]);
                B1[1] = fma2(c1, wdb, B1[1]);
                B1[2] = fma2(c2, wdb, B1[2]);
                B1[3] = fma2(c3, wdb, B1[3]);
            }
        }
    }
    #pragma unroll
    for (int p = 0; p < 4; p++) {
        float o0, o1, o2, o3;
        unpack2(B0[p], o0, o1);
        unpack2(B1[p], o2, o3);
        int n0 = nb + 2 * p;
        if (n0 < N_NODES) {
            out[(size_t)n0 * HID + j]  = o0;
            out[(size_t)n0 * HID + j2] = o2;
        }
        if (n0 + 1 < N_NODES) {
            out[(size_t)(n0 + 1) * HID + j]  = o1;
            out[(size_t)(n0 + 1) * HID + j2] = o3;
        }
    }
}

// ---------------------------------------------------------------------------
extern "C" void kernel_launch(void* const* d_in, const int* in_sizes, int n_in,
                              void* d_out, int out_size) {
    const int*   edge_index = (const int*)d_in[0];
    const float* edge_attr  = (const float*)d_in[1];
    const float* x          = (const float*)d_in[2];
    const float* W1         = (const float*)d_in[3];
    const float* b1         = (const float*)d_in[4];
    const float* W2         = (const float*)d_in[5];
    const float* b2         = (const float*)d_in[6];

    float* out      = (float*)d_out;
    float* combined = out + (size_t)N_NODES * HID;

    cudaMemsetAsync(combined, 0, (size_t)N_NODES * CDIM * sizeof(float));

    {
        int smem = (HID * HID) * 4 + NTILE * 16 * 16;
        cudaFuncSetAttribute(scatter_gemm_kernel,
                             cudaFuncAttributeMaxDynamicSharedMemorySize, smem);
        scatter_gemm_kernel<<<TOTAL_BLOCKS, 256, smem>>>(
            edge_index, (const float4*)edge_attr, (const float4*)x,
            W1, b1, combined);
    }

    {
        int smem = (2 * HID * SW_PAD + HID * SC_PAD) * (int)sizeof(float);
        cudaFuncSetAttribute(mlp2_kernel,
                             cudaFuncAttributeMaxDynamicSharedMemorySize, smem);
        mlp2_kernel<<<N2_TILES, 256, smem>>>(combined, W1, W2, b2, out);
    }
}

// round 7
// speedup vs baseline: 1.2332x; 1.0122x over previous
#include <cuda_runtime.h>
#include <cuda_bf16.h>

#define N_NODES 50000
#define N_EDGES 1250000
#define HID 64
#define CDIM 128
#define NTILE 32                                     // K1 GEMM tile
#define N_TILES ((N_NODES + NTILE - 1) / NTILE)
#define SCAT_BLOCKS 444
#define GEMM_BLOCKS 148
#define TOTAL_BLOCKS (SCAT_BLOCKS + GEMM_BLOCKS)
#define TOTAL_ITEMS (16LL * N_EDGES)
#define SPLIT_ITEMS 17500000LL

#define NT2 64                                       // mlp2 nodes per tile
#define N2_TILES ((N_NODES + NT2 - 1) / NT2)         // 782
#define MLP_GRID 608                                 // one full wave (152 SMs x 4)
#define SW_PAD 68   // weight row pad (words)
#define SC_PAD 68   // activation row pad (words): 16B-aligned rows for LDS.128

// scratch: t1 = x @ W1[0:64] + b1
__device__ float d_t1[(size_t)N_NODES * HID];

// ---------------- f32x2 helpers --------------------------------------------
typedef unsigned long long ull;
__device__ __forceinline__ ull pack2(float lo, float hi) {
    ull r; asm("mov.b64 %0, {%1, %2};" : "=l"(r) : "f"(lo), "f"(hi)); return r;
}
__device__ __forceinline__ void unpack2(ull v, float& lo, float& hi) {
    asm("mov.b64 {%0, %1}, %2;" : "=f"(lo), "=f"(hi) : "l"(v));
}
__device__ __forceinline__ ull fma2(ull a, ull b, ull c) {
    ull d; asm("fma.rn.f32x2 %0, %1, %2, %3;" : "=l"(d) : "l"(a), "l"(b), "l"(c));
    return d;
}

// ---------------------------------------------------------------------------
// scatter: sequential edge_attr stream + v4 reductions
// ---------------------------------------------------------------------------
__device__ __forceinline__ void scatter_range(const int* __restrict__ row,
                                              const float4* __restrict__ attr4,
                                              float* __restrict__ combined,
                                              long long beg, long long end,
                                              long long idx0, long long stride) {
    int lane = threadIdx.x & 31;
    int g = (int)((beg + idx0) & 15);
    long long idx = beg + idx0;

    while (idx - lane + 31 < end) {
        int e = (int)(idx >> 4);
        int r;
        if ((lane & 15) == 0) r = __ldg(row + e);
        r = __shfl_sync(0xffffffffu, r, lane & 16);
        float4 v = __ldg(attr4 + idx);
        float* dst = combined + (size_t)r * CDIM + HID + g * 4;
        asm volatile("red.global.add.v4.f32 [%0], {%1, %2, %3, %4};"
                     :: "l"(dst), "f"(v.x), "f"(v.y), "f"(v.z), "f"(v.w)
                     : "memory");
        idx += stride;
    }
    if (idx < end) {
        int e = (int)(idx >> 4);
        int r = __ldg(row + e);
        float4 v = __ldg(attr4 + idx);
        float* dst = combined + (size_t)r * CDIM + HID + g * 4;
        asm volatile("red.global.add.v4.f32 [%0], {%1, %2, %3, %4};"
                     :: "l"(dst), "f"(v.x), "f"(v.y), "f"(v.z), "f"(v.w)
                     : "memory");
    }
}

// ---------------------------------------------------------------------------
// K1: fused scatter + t1-GEMM (+ combined[:,0:64] = x copy)
// ---------------------------------------------------------------------------
__global__ void scatter_gemm_kernel(const int* __restrict__ row,
                                    const float4* __restrict__ attr4,
                                    const float4* __restrict__ x4,
                                    const float* __restrict__ W1,
                                    const float* __restrict__ b1,
                                    float* __restrict__ combined) {
    int tid = threadIdx.x;

    if (blockIdx.x < SCAT_BLOCKS) {
        long long idx0 = (long long)blockIdx.x * 256 + tid;
        scatter_range(row, attr4, combined, 0, SPLIT_ITEMS,
                      idx0, (long long)SCAT_BLOCKS * 256);
        return;
    }

    extern __shared__ float4 smem4[];
    float*  sW  = (float*)smem4;
    float4* sx4 = smem4 + (HID * HID) / 4;

    for (int i = tid; i < HID * HID; i += 256) sW[i] = W1[i];
    float bj = __ldg(b1 + (tid & 63));
    __syncthreads();

    int g = tid >> 6;
    int j = tid & 63;
    int bid = blockIdx.x - SCAT_BLOCKS;
    float4* comb4 = (float4*)combined;

    for (int tile = bid; tile < N_TILES; tile += GEMM_BLOCKS) {
        int node0 = tile * NTILE;
        for (int i = tid; i < NTILE * 16; i += 256) {
            int n = node0 + (i >> 4), q = i & 15;
            float4 v = make_float4(0.f, 0.f, 0.f, 0.f);
            if (n < N_NODES) {
                v = __ldg(x4 + (size_t)n * 16 + q);
                comb4[(size_t)n * 32 + q] = v;
            }
            sx4[i] = v;
        }
        __syncthreads();

        float acc[8];
        #pragma unroll
        for (int n = 0; n < 8; n++) acc[n] = bj;

        const float4* c0 = sx4 + g * 8 * 16;
        #pragma unroll 4
        for (int i4 = 0; i4 < 16; i4++) {
            float w0 = sW[(i4 * 4 + 0) * HID + j];
            float w1 = sW[(i4 * 4 + 1) * HID + j];
            float w2 = sW[(i4 * 4 + 2) * HID + j];
            float w3 = sW[(i4 * 4 + 3) * HID + j];
            #pragma unroll
            for (int n = 0; n < 8; n++) {
                float4 c = c0[n * 16 + i4];
                acc[n] = fmaf(c.x, w0, acc[n]);
                acc[n] = fmaf(c.y, w1, acc[n]);
                acc[n] = fmaf(c.z, w2, acc[n]);
                acc[n] = fmaf(c.w, w3, acc[n]);
            }
        }
        #pragma unroll
        for (int n = 0; n < 8; n++) {
            int node = node0 + g * 8 + n;
            if (node < N_NODES) d_t1[(size_t)node * HID + j] = acc[n];
        }
        __syncthreads();
    }

    long long idx0 = (long long)bid * 256 + tid;
    scatter_range(row, attr4, combined, SPLIT_ITEMS, TOTAL_ITEMS,
                  idx0, (long long)GEMM_BLOCKS * 256);
}

// ---------------------------------------------------------------------------
// K2: out = silu(t1 + agg @ W1b) @ W2 + b2
// 64-node tile; thread = 8 nodes x 2 features (j, j+32).
// Activations transposed in smem; LDS.128 (ulonglong2) broadcast loads feed
// f32x2 FMAs. h overlays agg buffer. Grid = 608 (one wave), 2-tile loop.
// ---------------------------------------------------------------------------
__global__ void __launch_bounds__(256, 4)
mlp2_kernel(const float* __restrict__ combined,
            const float* __restrict__ W1,
            const float* __restrict__ W2,
            const float* __restrict__ b2,
            float* __restrict__ out) {
    extern __shared__ float smem[];
    float* sW1T = smem;                         // [64][SW_PAD]
    float* sW2T = sW1T + HID * SW_PAD;          // [64][SW_PAD]
    float* scT  = sW2T + HID * SW_PAD;          // [64][SC_PAD] (agg, then h)

    int tid = threadIdx.x;

    for (int i = tid; i < HID * HID; i += 256) {
        int k = i >> 6, j = i & 63;
        sW1T[j * SW_PAD + k] = W1[(HID + k) * HID + j];   // W1b
        sW2T[j * SW_PAD + k] = W2[k * HID + j];
    }

    int g  = tid >> 5;          // node subgroup 0..7 (8 nodes)
    int j  = tid & 31;          // feature a
    int j2 = j + 32;            // feature b
    float b2a = __ldg(b2 + j);
    float b2b = __ldg(b2 + j2);
    ull b2da = pack2(b2a, b2a);
    ull b2db = pack2(b2b, b2b);

    const float4* comb4 = (const float4*)combined;
    bool first = true;

    for (int tile = blockIdx.x; tile < N2_TILES; tile += MLP_GRID) {
        int node0 = tile * NT2;
        int nb = node0 + g * 8;

        if (!first) __syncthreads();   // prior layer-2 scT reads done
        first = false;

        // ---- stage agg transposed: scT[k][n] = combined[node0+n][64+k] ----
        for (int s = tid; s < NT2 * 16; s += 256) {
            int n = s >> 4, q = s & 15;
            int node = node0 + n;
            float4 v = (node < N_NODES)
                         ? __ldg(comb4 + (size_t)node * 32 + 16 + q)
                         : make_float4(0.f, 0.f, 0.f, 0.f);
            scT[(q * 4 + 0) * SC_PAD + n] = v.x;
            scT[(q * 4 + 1) * SC_PAD + n] = v.y;
            scT[(q * 4 + 2) * SC_PAD + n] = v.z;
            scT[(q * 4 + 3) * SC_PAD + n] = v.w;
        }

        // ---- t1 prefetch ----
        ull A0[4], A1[4];
        #pragma unroll
        for (int p = 0; p < 4; p++) {
            int n0 = nb + 2 * p;
            float a0 = 0.f, a1 = 0.f, c0 = 0.f, c1 = 0.f;
            if (n0 < N_NODES) {
                a0 = d_t1[(size_t)n0 * HID + j];
                c0 = d_t1[(size_t)n0 * HID + j2];
            }
            if (n0 + 1 < N_NODES) {
                a1 = d_t1[(size_t)(n0 + 1) * HID + j];
                c1 = d_t1[(size_t)(n0 + 1) * HID + j2];
            }
            A0[p] = pack2(a0, a1);
            A1[p] = pack2(c0, c1);
        }
        __syncthreads();

        // ---- layer 1b ----
        {
            const float* wra = sW1T + j  * SW_PAD;
            const float* wrb = sW1T + j2 * SW_PAD;
            #pragma unroll 4
            for (int k4 = 0; k4 < 16; k4++) {
                float4 wa = *(const float4*)(wra + k4 * 4);
                float4 wb = *(const float4*)(wrb + k4 * 4);
                #pragma unroll
                for (int kk = 0; kk < 4; kk++) {
                    const float* base = scT + (k4 * 4 + kk) * SC_PAD + g * 8;
                    ulonglong2 cA = *(const ulonglong2*)(base);
                    ulonglong2 cB = *(const ulonglong2*)(base + 4);
                    float wka = (&wa.x)[kk];
                    float wkb = (&wb.x)[kk];
                    ull wda = pack2(wka, wka);
                    ull wdb = pack2(wkb, wkb);
                    A0[0] = fma2(cA.x, wda, A0[0]);
                    A0[1] = fma2(cA.y, wda, A0[1]);
                    A0[2] = fma2(cB.x, wda, A0[2]);
                    A0[3] = fma2(cB.y, wda, A0[3]);
                    A1[0] = fma2(cA.x, wdb, A1[0]);
                    A1[1] = fma2(cA.y, wdb, A1[1]);
                    A1[2] = fma2(cB.x, wdb, A1[2]);
                    A1[3] = fma2(cB.y, wdb, A1[3]);
                }
            }
        }
        __syncthreads();   // all scT reads complete before overwrite with h

        // ---- SiLU; store h transposed into scT (reuse) ----
        #pragma unroll
        for (int p = 0; p < 4; p++) {
            float a0, a1, c0, c1;
            unpack2(A0[p], a0, a1);
            unpack2(A1[p], c0, c1);
            float h0 = __fdividef(a0, 1.0f + __expf(-a0));
            float h1 = __fdividef(a1, 1.0f + __expf(-a1));
            float h2 = __fdividef(c0, 1.0f + __expf(-c0));
            float h3 = __fdividef(c1, 1.0f + __expf(-c1));
            *(ull*)(scT + j  * SC_PAD + g * 8 + 2 * p) = pack2(h0, h1);
            *(ull*)(scT + j2 * SC_PAD + g * 8 + 2 * p) = pack2(h2, h3);
        }
        __syncthreads();

        // ---- layer 2 ----
        ull B0[4], B1[4];
        #pragma unroll
        for (int p = 0; p < 4; p++) { B0[p] = b2da; B1[p] = b2db; }
        {
            const float* wra = sW2T + j  * SW_PAD;
            const float* wrb = sW2T + j2 * SW_PAD;
            #pragma unroll 4
            for (int k4 = 0; k4 < 16; k4++) {
                float4 wa = *(const float4*)(wra + k4 * 4);
                float4 wb = *(const float4*)(wrb + k4 * 4);
                #pragma unroll
                for (int kk = 0; kk < 4; kk++) {
                    const float* base = scT + (k4 * 4 + kk) * SC_PAD + g * 8;
                    ulonglong2 cA = *(const ulonglong2*)(base);
                    ulonglong2 cB = *(const ulonglong2*)(base + 4);
                    float wka = (&wa.x)[kk];
                    float wkb = (&wb.x)[kk];
                    ull wda = pack2(wka, wka);
                    ull wdb = pack2(wkb, wkb);
                    B0[0] = fma2(cA.x, wda, B0[0]);
                    B0[1] = fma2(cA.y, wda, B0[1]);
                    B0[2] = fma2(cB.x, wda, B0[2]);
                    B0[3] = fma2(cB.y, wda, B0[3]);
                    B1[0] = fma2(cA.x, wdb, B1[0]);
                    B1[1] = fma2(cA.y, wdb, B1[1]);
                    B1[2] = fma2(cB.x, wdb, B1[2]);
                    B1[3] = fma2(cB.y, wdb, B1[3]);
                }
            }
        }
        #pragma unroll
        for (int p = 0; p < 4; p++) {
            float o0, o1, o2, o3;
            unpack2(B0[p], o0, o1);
            unpack2(B1[p], o2, o3);
            int n0 = nb + 2 * p;
            if (n0 < N_NODES) {
                out[(size_t)n0 * HID + j]  = o0;
                out[(size_t)n0 * HID + j2] = o2;
            }
            if (n0 + 1 < N_NODES) {
                out[(size_t)(n0 + 1) * HID + j]  = o1;
                out[(size_t)(n0 + 1) * HID + j2] = o3;
            }
        }
    }
}

// ---------------------------------------------------------------------------
extern "C" void kernel_launch(void* const* d_in, const int* in_sizes, int n_in,
                              void* d_out, int out_size) {
    const int*   edge_index = (const int*)d_in[0];
    const float* edge_attr  = (const float*)d_in[1];
    const float* x          = (const float*)d_in[2];
    const float* W1         = (const float*)d_in[3];
    const float* b1         = (const float*)d_in[4];
    const float* W2         = (const float*)d_in[5];
    const float* b2         = (const float*)d_in[6];

    float* out      = (float*)d_out;
    float* combined = out + (size_t)N_NODES * HID;

    cudaMemsetAsync(combined, 0, (size_t)N_NODES * CDIM * sizeof(float));

    {
        int smem = (HID * HID) * 4 + NTILE * 16 * 16;
        cudaFuncSetAttribute(scatter_gemm_kernel,
                             cudaFuncAttributeMaxDynamicSharedMemorySize, smem);
        scatter_gemm_kernel<<<TOTAL_BLOCKS, 256, smem>>>(
            edge_index, (const float4*)edge_attr, (const float4*)x,
            W1, b1, combined);
    }

    {
        int smem = (2 * HID * SW_PAD + HID * SC_PAD) * (int)sizeof(float);
        cudaFuncSetAttribute(mlp2_kernel,
                             cudaFuncAttributeMaxDynamicSharedMemorySize, smem);
        mlp2_kernel<<<MLP_GRID, 256, smem>>>(combined, W1, W2, b2, out);
    }
}